// round 1
// baseline (speedup 1.0000x reference)
#include <cuda_runtime.h>
#include <math.h>

// ---------------------------------------------------------------------------
// ConvLSTM (2 layers, 12 steps) on GB300.
// Layer0: Cin=129 (x:1 + h0:128), hid=128  -> conv channels 512
// Layer1: Cin=140 (h0:128 + h1:12), hid=12 -> conv channels 48
// Gate order along conv-channel axis: [i | f | o | g], each of size hid.
// c_next = sig(f)*c + sig(i)*tanh(g);  h_next = sig(o)*tanh(c_next)
// ---------------------------------------------------------------------------

#define HW     4096
#define BATCH  16
#define TSTEPS 12

// -------------------- device scratch (no allocations allowed) --------------
__device__ float g_h0[2u * 16u * 128u * 4096u];   // ping-pong h for layer0 (64MB)
__device__ float g_c0[16u * 128u * 4096u];        // c layer0, in-place (32MB)
__device__ float g_h1[2u * 16u * 12u * 4096u];    // ping-pong h for layer1
__device__ float g_c1[16u * 12u * 4096u];
__device__ float g_wp0[32u * 136u * 9u * 32u];    // repacked+dup weights L0 (5MB)
__device__ float g_wp1[3u  * 144u * 9u * 32u];    // repacked+dup weights L1

// -------------------- helpers: packed f32x2 --------------------------------
__device__ __forceinline__ unsigned long long pk2(float lo, float hi) {
    unsigned long long r;
    asm("mov.b64 %0, {%1,%2};" : "=l"(r) : "f"(lo), "f"(hi));
    return r;
}
__device__ __forceinline__ void fma2(unsigned long long& d,
                                     unsigned long long a,
                                     unsigned long long b) {
    asm("fma.rn.f32x2 %0, %1, %2, %0;" : "+l"(d) : "l"(a), "l"(b));
}
__device__ __forceinline__ float2 up2(unsigned long long v) {
    float2 f;
    asm("mov.b64 {%0,%1}, %2;" : "=f"(f.x), "=f"(f.y) : "l"(v));
    return f;
}
__device__ __forceinline__ float sigf(float x) {
    return 1.0f / (1.0f + __expf(-x));
}

// -------------------- init / repack ----------------------------------------
__global__ void zero_init_kernel() {
    size_t tid = (size_t)blockIdx.x * blockDim.x + threadIdx.x;
    size_t stride = (size_t)gridDim.x * blockDim.x;
    const size_t n0 = (size_t)16 * 128 * 4096;
    const size_t n1 = (size_t)16 * 12 * 4096;
    for (size_t i = tid; i < n0; i += stride) { g_h0[i] = 0.f; g_c0[i] = 0.f; }
    for (size_t i = tid; i < n1; i += stride) { g_h1[i] = 0.f; g_c1[i] = 0.f; }
}

// Repack W[(4*HID), CIN, 3, 3] -> Wp[hidblk][cinp][tap(9)][hl(4)][gate(4)][dup(2)]
// Each weight duplicated into both f32x2 halves so the inner loop needs no packs.
__global__ void repack_kernel(const float* __restrict__ W, float* __restrict__ Wp,
                              int HID, int CIN, int CINP) {
    int total = (HID / 4) * CINP * 9 * 32;
    for (int idx = blockIdx.x * blockDim.x + threadIdx.x; idx < total;
         idx += gridDim.x * blockDim.x) {
        int g   = (idx >> 1) & 3;
        int hl  = (idx >> 3) & 3;
        int t   = idx >> 5;          // (hidblk*CINP + cin)*9 + tap
        int tap = t % 9;
        int ci  = t / 9;
        int cin = ci % CINP;
        int hb  = ci / CINP;
        int hid = hb * 4 + hl;
        float v = 0.f;
        if (cin < CIN) v = W[((size_t)(g * HID + hid) * CIN + cin) * 9 + tap];
        Wp[idx] = v;
    }
}

// -------------------- fused conv + LSTM gate step ---------------------------
// Block: 128 threads = (tx:8)x(ty:8)x(tz:2). Spatial tile 32x8.
// Block covers 4 hid channels (tz selects a pair, h in {0,1} the channel).
// Thread: 4 consecutive x pixels, 2 hid, 4 gates -> 16 f32x2 accumulators.
template <int CINP, int CIN, int CA, int HID>
__global__ __launch_bounds__(128)
void convlstm_step(const float* __restrict__ srcA, int bstrA,
                   const float* __restrict__ srcB,
                   const float* __restrict__ Wp,
                   const float* __restrict__ bias,
                   float* __restrict__ cbuf,
                   float* __restrict__ hout) {
    __shared__ __align__(16) float in_s[8][10][36];   // 8 cin x (8+2) rows x (32+2 used)
    __shared__ __align__(16) float w_s[8 * 9 * 32];   // 8 cin x 9 taps x 32 (dup'd)

    const int tid = threadIdx.x;
    const int tx  = tid & 7;
    const int ty  = (tid >> 3) & 7;
    const int tz  = tid >> 6;

    const int tile = blockIdx.x;     // 0..15
    const int hb   = blockIdx.y;
    const int b    = blockIdx.z;

    const int x0 = (tile & 1) * 32;
    const int y0 = (tile >> 1) * 8;

    const float* baseA = srcA + (size_t)b * bstrA;
    const float* baseB = srcB + (size_t)b * (CIN - CA) * HW;
    const float* wbase = Wp + (size_t)hb * CINP * 288;

    unsigned long long acc[2][4][2];
#pragma unroll
    for (int h = 0; h < 2; h++)
#pragma unroll
        for (int g = 0; g < 4; g++)
#pragma unroll
            for (int p = 0; p < 2; p++) acc[h][g][p] = 0ull;

    const int NCH = CINP / 8;
    for (int ch = 0; ch < NCH; ch++) {
        __syncthreads();
        // ---- load input tile (with halo, zero-padded at borders / cin>=CIN)
        {
            const int cbase = ch * 8;
            for (int idx = tid; idx < 8 * 340; idx += 128) {
                int ck  = idx / 340;
                int rem = idx - ck * 340;
                int r   = rem / 34;
                int cc  = rem - r * 34;
                int cin = cbase + ck;
                int gy  = y0 + r - 1;
                int gx  = x0 + cc - 1;
                float v = 0.f;
                if (cin < CIN && (unsigned)gy < 64u && (unsigned)gx < 64u) {
                    int pix = gy * 64 + gx;
                    v = (cin < CA) ? baseA[(size_t)cin * HW + pix]
                                   : baseB[(size_t)(cin - CA) * HW + pix];
                }
                in_s[ck][r][cc] = v;
            }
            // ---- load weights (2304 floats)
            const float4* wsrc = (const float4*)(wbase + (size_t)ch * 8 * 288);
            float4* wdst = (float4*)w_s;
            for (int idx = tid; idx < 576; idx += 128) wdst[idx] = wsrc[idx];
        }
        __syncthreads();

#pragma unroll
        for (int ck = 0; ck < 8; ck++) {
#pragma unroll
            for (int ky = 0; ky < 3; ky++) {
                const float* ip = &in_s[ck][ty + ky][tx * 4];
                float4 v4 = *(const float4*)ip;
                float2 v2 = *(const float2*)(ip + 4);
                unsigned long long p01 = pk2(v4.x, v4.y);
                unsigned long long p12 = pk2(v4.y, v4.z);
                unsigned long long p23 = pk2(v4.z, v4.w);
                unsigned long long p34 = pk2(v4.w, v2.x);
                unsigned long long p45 = pk2(v2.x, v2.y);
                unsigned long long pA[3] = {p01, p12, p23};
                unsigned long long pB[3] = {p23, p34, p45};
#pragma unroll
                for (int kx = 0; kx < 3; kx++) {
#pragma unroll
                    for (int h = 0; h < 2; h++) {
                        const float* wp =
                            &w_s[((ck * 3 + ky) * 3 + kx) * 32 + (tz * 2 + h) * 8];
                        ulonglong2 wva = *(const ulonglong2*)(wp);      // g0dup,g1dup
                        ulonglong2 wvb = *(const ulonglong2*)(wp + 4);  // g2dup,g3dup
                        fma2(acc[h][0][0], pA[kx], wva.x);
                        fma2(acc[h][0][1], pB[kx], wva.x);
                        fma2(acc[h][1][0], pA[kx], wva.y);
                        fma2(acc[h][1][1], pB[kx], wva.y);
                        fma2(acc[h][2][0], pA[kx], wvb.x);
                        fma2(acc[h][2][1], pB[kx], wvb.x);
                        fma2(acc[h][3][0], pA[kx], wvb.y);
                        fma2(acc[h][3][1], pB[kx], wvb.y);
                    }
                }
            }
        }
    }

    // ---- epilogue: gates + state update
    const int y  = y0 + ty;
    const int xb = x0 + tx * 4;
#pragma unroll
    for (int h = 0; h < 2; h++) {
        const int hid = hb * 4 + tz * 2 + h;
        const float bi = bias[0 * HID + hid];
        const float bf = bias[1 * HID + hid];
        const float bo = bias[2 * HID + hid];
        const float bg = bias[3 * HID + hid];

        float iv[4], fv[4], ov[4], gv[4];
#pragma unroll
        for (int p = 0; p < 2; p++) {
            float2 fi = up2(acc[h][0][p]);
            float2 ff = up2(acc[h][1][p]);
            float2 fo = up2(acc[h][2][p]);
            float2 fg = up2(acc[h][3][p]);
            iv[p * 2] = fi.x; iv[p * 2 + 1] = fi.y;
            fv[p * 2] = ff.x; fv[p * 2 + 1] = ff.y;
            ov[p * 2] = fo.x; ov[p * 2 + 1] = fo.y;
            gv[p * 2] = fg.x; gv[p * 2 + 1] = fg.y;
        }

        const size_t base = ((size_t)(b * HID + hid)) * HW + y * 64 + xb;
        float4 c4 = *(const float4*)(cbuf + base);
        float co[4] = {c4.x, c4.y, c4.z, c4.w};
        float cn[4], hn[4];
#pragma unroll
        for (int p = 0; p < 4; p++) {
            float I = sigf(iv[p] + bi);
            float F = sigf(fv[p] + bf);
            float O = sigf(ov[p] + bo);
            float G = tanhf(gv[p] + bg);
            float c_new = F * co[p] + I * G;
            cn[p] = c_new;
            hn[p] = O * tanhf(c_new);
        }
        *(float4*)(cbuf + base) = make_float4(cn[0], cn[1], cn[2], cn[3]);
        *(float4*)(hout + base) = make_float4(hn[0], hn[1], hn[2], hn[3]);
    }
}

// -------------------- host driver -------------------------------------------
extern "C" void kernel_launch(void* const* d_in, const int* in_sizes, int n_in,
                              void* d_out, int out_size) {
    (void)in_sizes; (void)n_in; (void)out_size;
    const float* history = (const float*)d_in[0];
    const float* W0 = (const float*)d_in[2];
    const float* b0 = (const float*)d_in[3];
    const float* W1 = (const float*)d_in[4];
    const float* b1 = (const float*)d_in[5];

    float *h0, *c0, *h1, *c1, *wp0, *wp1;
    cudaGetSymbolAddress((void**)&h0,  g_h0);
    cudaGetSymbolAddress((void**)&c0,  g_c0);
    cudaGetSymbolAddress((void**)&h1,  g_h1);
    cudaGetSymbolAddress((void**)&c1,  g_c1);
    cudaGetSymbolAddress((void**)&wp0, g_wp0);
    cudaGetSymbolAddress((void**)&wp1, g_wp1);

    zero_init_kernel<<<1024, 256>>>();
    repack_kernel<<<512, 256>>>(W0, wp0, 128, 129, 136);
    repack_kernel<<<64, 256>>>(W1, wp1, 12, 140, 144);

    const size_t H0SZ = (size_t)16 * 128 * 4096;
    const size_t H1SZ = (size_t)16 * 12 * 4096;

    int pa = 0;
    for (int t = 0; t < TSTEPS; t++) {
        const float* h0r = h0 + (size_t)pa * H0SZ;
        float*       h0w = h0 + (size_t)(1 - pa) * H0SZ;
        const float* h1r = h1 + (size_t)pa * H1SZ;
        float*       h1w = h1 + (size_t)(1 - pa) * H1SZ;

        // Layer 0: x_t (1ch) + h0 (128ch) -> hid 128
        convlstm_step<136, 129, 1, 128><<<dim3(16, 32, 16), 128>>>(
            history + (size_t)t * HW, TSTEPS * HW, h0r, wp0, b0, c0, h0w);

        // Layer 1: h0_cur (128ch) + h1 (12ch) -> hid 12
        convlstm_step<144, 140, 128, 12><<<dim3(16, 3, 16), 128>>>(
            h0w, 128 * HW, h1r, wp1, b1, c1, h1w);

        pa ^= 1;
    }

    // After 12 steps the last write landed in buffer 0 of g_h1; its layout
    // (B, hid=12, 64*64) is exactly the required (B, L=12, N=4096, 1).
    cudaMemcpyAsync(d_out, h1, H1SZ * sizeof(float), cudaMemcpyDeviceToDevice);
}